// round 9
// baseline (speedup 1.0000x reference)
#include <cuda_runtime.h>
#include <cstdint>

// out[m, e*32+k] = sum_n A[m,n] * W[e,n,k]
// => C[8192,2048] = A[8192,1024] x B[1024,2048], B[n, e*32+k] = W[e,n,k]
// mma.sync.m16n8k8 tf32; 128x128 CTA tile, 4 warps (64x64), 3 stages, 2 CTAs/SM.
// R9: compile-time stage offsets (3-phase unrolled k-loop) so ptxas folds all
//     ldsm/cp.async addressing into immediates; specialized tail iterations.

#define M_DIM 8192
#define KR    1024
#define NOUT  2048
#define E_DIM 64

#define BM 128
#define BN 128
#define BK 32
#define STAGES 3
#define KTILES (KR / BK)                 // 32

#define A_STAGE (BM * BK * 4)            // 16 KB
#define B_STAGE (BN * BK * 4)            // 16 KB
#define STAGE_BYTES (A_STAGE + B_STAGE)  // 32 KB
#define SMEM_TOTAL (STAGES * STAGE_BYTES)// 96 KB -> 2 CTAs/SM

__device__ float g_Bt[(size_t)NOUT * KR];    // 8 MB: W transposed+rounded, [col][n]

// ---------------- helpers ----------------
__device__ __forceinline__ uint32_t smem_u32(const void* p) {
    uint32_t a;
    asm("{ .reg .u64 t; cvta.to.shared.u64 t, %1; cvt.u32.u64 %0, t; }" : "=r"(a) : "l"(p));
    return a;
}
__device__ __forceinline__ float tf32_rna(float x) {
    float y; asm("cvt.rna.tf32.f32 %0, %1;" : "=f"(y) : "f"(x)); return y;
}
__device__ __forceinline__ void cp16(uint32_t dst, const void* src) {
    asm volatile("cp.async.cg.shared.global [%0], [%1], 16;" :: "r"(dst), "l"(src) : "memory");
}
#define CP_COMMIT() asm volatile("cp.async.commit_group;" ::: "memory")
#define CP_WAIT0()  asm volatile("cp.async.wait_group 0;" ::: "memory")
#define CP_WAIT1()  asm volatile("cp.async.wait_group 1;" ::: "memory")

__device__ __forceinline__ void ldsm4(uint32_t* r, uint32_t addr) {
    asm volatile("ldmatrix.sync.aligned.m8n8.x4.shared.b16 {%0,%1,%2,%3}, [%4];"
                 : "=r"(r[0]), "=r"(r[1]), "=r"(r[2]), "=r"(r[3]) : "r"(addr));
}
__device__ __forceinline__ void mma8(float* c, const uint32_t* a, uint32_t b0, uint32_t b1) {
    asm volatile("mma.sync.aligned.m16n8k8.row.col.f32.tf32.tf32.f32 "
                 "{%0,%1,%2,%3}, {%4,%5,%6,%7}, {%8,%9}, {%0,%1,%2,%3};"
                 : "+f"(c[0]), "+f"(c[1]), "+f"(c[2]), "+f"(c[3])
                 : "r"(a[0]), "r"(a[1]), "r"(a[2]), "r"(a[3]), "r"(b0), "r"(b1));
}
// swizzled byte offset for K-major tile, 128B rows: row r, 16B chunk c
__device__ __forceinline__ uint32_t swoff(int r, int c) {
    return (uint32_t)(r * 128 + ((c ^ (r & 7)) << 4));
}

// ---------------- prep kernel ----------------
__global__ void transpose_round_W(const float* __restrict__ W) {
    __shared__ float t[32][33];
    const int e = blockIdx.y;
    const int n0 = blockIdx.x * 32;
    const int tid = threadIdx.x;            // 256
    {
        const int i = tid >> 3, k4 = (tid & 7) * 4;
        float4 v = *(const float4*)(W + ((size_t)e * KR + n0 + i) * 32 + k4);
        t[i][k4 + 0] = tf32_rna(v.x);
        t[i][k4 + 1] = tf32_rna(v.y);
        t[i][k4 + 2] = tf32_rna(v.z);
        t[i][k4 + 3] = tf32_rna(v.w);
    }
    __syncthreads();
    {
        const int k = tid >> 3, j4 = (tid & 7) * 4;
        float4 o = make_float4(t[j4 + 0][k], t[j4 + 1][k], t[j4 + 2][k], t[j4 + 3][k]);
        *(float4*)(g_Bt + ((size_t)(e * 32 + k)) * KR + n0 + j4) = o;
    }
}

// ---------------- main GEMM ----------------
__global__ __launch_bounds__(128, 2)
void gemm_tf32_mma(const float* __restrict__ A, float* __restrict__ out) {
    extern __shared__ char smem[];
    const uint32_t sb = smem_u32(smem);
    const int tid  = threadIdx.x;
    const int lane = tid & 31;
    const int wid  = tid >> 5;
    const int warp_m = wid & 1;     // 2 warps over M  -> 64 rows each
    const int warp_n = wid >> 1;    // 2 warps over N  -> 64 cols each
    const int rowBase = blockIdx.y * BM;
    const int colBase = blockIdx.x * BN;

    // ---- loop-invariant cp.async addressing ----
    const int ldr = tid >> 3;                 // 0..15
    const int ldc = tid & 7;                  // 16B chunk
    const float* aSrc = A    + ((size_t)rowBase + ldr) * KR + ldc * 4;
    const float* bSrc = g_Bt + ((size_t)colBase + ldr) * KR + ldc * 4;
    const uint32_t aDst0 = sb + swoff(ldr, ldc);            // +2048*i for row+16i
    const uint32_t bDst0 = sb + A_STAGE + swoff(ldr, ldc);

    // ---- loop-invariant ldsm addressing ----
    const int lrow  = ((lane >> 3) & 1) * 8 + (lane & 7);
    const int lxor  = lane & 7;
    const int lhalf = lane >> 4;
    const uint32_t aBase = sb + (uint32_t)((warp_m * 64 + lrow) * 128);
    const uint32_t bBase = sb + A_STAGE + (uint32_t)((warp_n * 64 + lrow) * 128);
    uint32_t coff[4];
    #pragma unroll
    for (int ks = 0; ks < 4; ks++)
        coff[ks] = (uint32_t)(((ks * 2 + lhalf) ^ lxor) << 4);

    float acc[4][8][4];
    #pragma unroll
    for (int mi = 0; mi < 4; mi++)
        #pragma unroll
        for (int ni = 0; ni < 8; ni++)
            #pragma unroll
            for (int q = 0; q < 4; q++) acc[mi][ni][q] = 0.0f;

    // ---- fragment buffers (parity double-buffered, static indices) ----
    uint32_t a0[4][4], a1[4][4], b0[4][4], b1[4][4];

#define LDFRAG0(soff, ks) do { \
    _Pragma("unroll") for (int mi = 0; mi < 4; mi++) \
        ldsm4(a0[mi], aBase + (soff) + mi * 2048u + coff[ks]); \
    _Pragma("unroll") for (int nb = 0; nb < 4; nb++) \
        ldsm4(b0[nb], bBase + (soff) + nb * 2048u + coff[ks]); \
} while (0)
#define LDFRAG1(soff, ks) do { \
    _Pragma("unroll") for (int mi = 0; mi < 4; mi++) \
        ldsm4(a1[mi], aBase + (soff) + mi * 2048u + coff[ks]); \
    _Pragma("unroll") for (int nb = 0; nb < 4; nb++) \
        ldsm4(b1[nb], bBase + (soff) + nb * 2048u + coff[ks]); \
} while (0)
#define MMA_BURST(ab, bb) do { \
    _Pragma("unroll") for (int mi = 0; mi < 4; mi++) \
        _Pragma("unroll") for (int nb = 0; nb < 4; nb++) { \
            mma8(acc[mi][nb * 2 + 0], ab[mi], bb[nb][0], bb[nb][2]); \
            mma8(acc[mi][nb * 2 + 1], ab[mi], bb[nb][1], bb[nb][3]); \
        } \
} while (0)

    // ---- producer: issue one stage's cp.asyncs (all offsets literal) ----
#define ISSUE_STAGE(PROD, SRCOFF) do { \
    _Pragma("unroll") for (int i = 0; i < 8; i++) \
        cp16(aDst0 + (PROD) + i * 2048u, aP + (size_t)i * 16 * KR + (SRCOFF)); \
    _Pragma("unroll") for (int i = 0; i < 8; i++) \
        cp16(bDst0 + (PROD) + i * 2048u, bP + (size_t)i * 16 * KR + (SRCOFF)); \
    CP_COMMIT(); \
} while (0)

    // One k-tile: CONS/PROD/NXT are literal stage byte-offsets, SRCOFF literal.
#define KT_ITER(CONS, PROD, NXT, SRCOFF) do { \
    LDFRAG1(CONS, 1); \
    MMA_BURST(a0, b0); \
    LDFRAG0(CONS, 2); \
    MMA_BURST(a1, b1); \
    CP_WAIT0(); \
    LDFRAG1(CONS, 3); \
    MMA_BURST(a0, b0); \
    __syncthreads(); \
    LDFRAG0(NXT, 0); \
    ISSUE_STAGE(PROD, SRCOFF); \
    MMA_BURST(a1, b1); \
} while (0)

    // ---- prologue: stages 0,1 in flight; wait s0; preload ks0 frags ----
    {
        const float* aP = aSrc; const float* bP = bSrc;
        ISSUE_STAGE(0, 0);
        ISSUE_STAGE(STAGE_BYTES, BK * 4 / 4);   // +BK floats
    }
    CP_WAIT1();
    __syncthreads();
    LDFRAG0(0, 0);

    const float* aP = aSrc + 2 * BK;   // src base for kt+2 issues
    const float* bP = bSrc + 2 * BK;

    #pragma unroll 1
    for (int kt3 = 0; kt3 < 10; kt3++) {
        KT_ITER(0,               2 * STAGE_BYTES, STAGE_BYTES,     0);
        KT_ITER(STAGE_BYTES,     0,               2 * STAGE_BYTES, BK);
        KT_ITER(2 * STAGE_BYTES, STAGE_BYTES,     0,               2 * BK);
        aP += 3 * BK; bP += 3 * BK;
    }

    // ---- kt = 30: consume stage 0, no issue, preload stage 1 frags ----
    LDFRAG1(0, 1);
    MMA_BURST(a0, b0);
    LDFRAG0(0, 2);
    MMA_BURST(a1, b1);
    CP_WAIT0();
    LDFRAG1(0, 3);
    MMA_BURST(a0, b0);
    __syncthreads();
    LDFRAG0(STAGE_BYTES, 0);
    MMA_BURST(a1, b1);

    // ---- kt = 31: consume stage 1, nothing outstanding ----
    LDFRAG1(STAGE_BYTES, 1);
    MMA_BURST(a0, b0);
    LDFRAG0(STAGE_BYTES, 2);
    MMA_BURST(a1, b1);
    LDFRAG1(STAGE_BYTES, 3);
    MMA_BURST(a0, b0);
    MMA_BURST(a1, b1);

    // ---- epilogue: direct stores (float2 per frag row) ----
    const int g = lane >> 2, t = lane & 3;
    #pragma unroll
    for (int mi = 0; mi < 4; mi++) {
        const int r0 = rowBase + warp_m * 64 + mi * 16 + g;
        #pragma unroll
        for (int ni = 0; ni < 8; ni++) {
            const int col = colBase + warp_n * 64 + ni * 8 + t * 2;
            *(float2*)(out + (size_t)r0 * NOUT + col) =
                make_float2(acc[mi][ni][0], acc[mi][ni][1]);
            *(float2*)(out + (size_t)(r0 + 8) * NOUT + col) =
                make_float2(acc[mi][ni][2], acc[mi][ni][3]);
        }
    }
}

extern "C" void kernel_launch(void* const* d_in, const int* in_sizes, int n_in,
                              void* d_out, int out_size)
{
    const float* A = (const float*)d_in[0];
    const float* W = (const float*)d_in[1];
    float* out = (float*)d_out;

    cudaFuncSetAttribute(gemm_tf32_mma, cudaFuncAttributeMaxDynamicSharedMemorySize, SMEM_TOTAL);

    transpose_round_W<<<dim3(KR / 32, E_DIM), 256>>>(W);
    gemm_tf32_mma<<<dim3(NOUT / BN, M_DIM / BM), 128, SMEM_TOTAL>>>(A, out);
}